// round 1
// baseline (speedup 1.0000x reference)
#include <cuda_runtime.h>

#define EMB   300
#define TASKS 12
#define POOL_THREADS 320

// Device-global scratch (no allocations allowed in kernel_launch).
__device__ int g_is64;
__device__ int g_starts[32769];  // starts[g] = first node index with batch >= g

// ---------------------------------------------------------------------------
// Detect whether batch is int64 or int32.
// Interpreted as int32 words: word[N-1] is
//   - int32 buffer: the last (max) graph id  -> > 0 (sorted ids ending ~16383)
//   - int64 buffer: the HIGH word of element (N-1)/2 -> 0 (ids < 2^31, >= 0)
// Reading word N-1 is in-bounds for both layouts.
// ---------------------------------------------------------------------------
__global__ void detect_kernel(const int* __restrict__ batch32, int N) {
    g_is64 = (batch32[N - 1] == 0) ? 1 : 0;
}

__device__ __forceinline__ long long load_batch(const void* bp, int i, int is64) {
    return is64 ? ((const long long*)bp)[i]
                : (long long)((const int*)bp)[i];
}

// ---------------------------------------------------------------------------
// Fill g_starts: for sorted batch, starts[g] = lower_bound(batch, g).
// Handles empty graphs (skipped ids) and trailing empty graphs.
// ---------------------------------------------------------------------------
__global__ void starts_kernel(const void* __restrict__ batch, int N, int G) {
    int i = blockIdx.x * blockDim.x + threadIdx.x;
    if (i >= N) return;
    int is64 = g_is64;
    long long cur  = load_batch(batch, i, is64);
    long long prev = (i > 0) ? load_batch(batch, i - 1, is64) : -1;
    for (long long g = prev + 1; g <= cur; ++g) {
        if (g >= 0 && g <= (long long)G) g_starts[g] = i;
    }
    if (i == N - 1) {
        for (long long g = cur + 1; g <= (long long)G; ++g) g_starts[g] = N;
    }
}

// ---------------------------------------------------------------------------
// One CTA per graph: stream-sum contiguous node rows (coalesced, 4x unrolled),
// then fused 300->12 linear head + mean-scale + bias in the epilogue.
// ---------------------------------------------------------------------------
__global__ __launch_bounds__(POOL_THREADS)
void pool_head_kernel(const float* __restrict__ x,
                      const float* __restrict__ W,
                      const float* __restrict__ b,
                      float* __restrict__ out) {
    int g = blockIdx.x;
    __shared__ float sh[EMB];

    int lo = g_starts[g];
    int hi = g_starts[g + 1];

    int t = threadIdx.x;
    if (t < EMB) {
        const float* p = x + (size_t)lo * EMB + t;
        float a0 = 0.f, a1 = 0.f, a2 = 0.f, a3 = 0.f;
        int r = lo;
        for (; r + 4 <= hi; r += 4) {
            a0 += p[0];
            a1 += p[EMB];
            a2 += p[2 * EMB];
            a3 += p[3 * EMB];
            p  += 4 * EMB;
        }
        for (; r < hi; ++r) { a0 += *p; p += EMB; }
        sh[t] = (a0 + a1) + (a2 + a3);
    }
    __syncthreads();

    int wid  = t >> 5;
    int lane = t & 31;
    float inv = 1.0f / fmaxf((float)(hi - lo), 1.0f);

    // 10 warps cover 12 tasks (warps 0,1 take a second task).
    for (int task = wid; task < TASKS; task += 10) {
        const float* wrow = W + task * EMB;
        float a = 0.f;
        #pragma unroll
        for (int d = lane; d < EMB; d += 32) {
            a += sh[d] * __ldg(&wrow[d]);
        }
        #pragma unroll
        for (int o = 16; o; o >>= 1) a += __shfl_xor_sync(0xffffffffu, a, o);
        if (lane == 0) {
            out[(size_t)g * TASKS + task] = a * inv + b[task];
        }
    }
}

// ---------------------------------------------------------------------------
// kernel_launch — inputs: x [N,300] f32, batch [N] int32/int64 (sorted),
// W [12,300] f32, b [12] f32, (num_graphs scalar, unused). out: [G,12] f32.
// ---------------------------------------------------------------------------
extern "C" void kernel_launch(void* const* d_in, const int* in_sizes, int n_in,
                              void* d_out, int out_size) {
    const float* x     = (const float*)d_in[0];
    const void*  batch = d_in[1];
    const float* W     = (const float*)d_in[2];
    const float* b     = (const float*)d_in[3];
    float*       out   = (float*)d_out;

    int N = in_sizes[1];            // node count (element count of batch)
    int G = out_size / TASKS;       // 16384

    detect_kernel<<<1, 1>>>((const int*)batch, N);
    starts_kernel<<<(N + 255) / 256, 256>>>(batch, N, G);
    pool_head_kernel<<<G, POOL_THREADS>>>(x, W, b, out);
}